// round 13
// baseline (speedup 1.0000x reference)
#include <cuda_runtime.h>
#include <cuda_fp16.h>
#include <cstdint>

#define B_    16384
#define CURD  2048
#define FEAT_ 2048
#define HEADS_ 16
#define HDIM  128

#define NTHREADS 256
#define BM 128
#define BN 128
#define BK 64
#define A_STAGE   16384
#define STAGE_B   (2*A_STAGE)          // 32 KB
#define SMEM_BYTES (2*STAGE_B)         // 64 KB (2 stages) -> 2 CTAs/SM
#define QS_STRIDE 132
#define SMEM_QATTN (128*QS_STRIDE*4)   // 67584 B fp32 q-tile (>= SMEM_BYTES)

// ---------------- scratch (device globals; no allocation allowed) ----------
__device__ __align__(16) __half g_xh [(size_t)B_*CURD];
__device__ __align__(16) __half g_v2h[(size_t)B_*FEAT_];
__device__ __align__(16) __half g_v3h[(size_t)B_*FEAT_];
__device__ __align__(16) __half g_wqh [(size_t)FEAT_*CURD];
__device__ __align__(16) __half g_wk2h[(size_t)FEAT_*FEAT_];
__device__ __align__(16) __half g_wv2h[(size_t)FEAT_*FEAT_];
__device__ __align__(16) __half g_wk3h[(size_t)FEAT_*FEAT_];
__device__ __align__(16) __half g_wv3h[(size_t)FEAT_*FEAT_];
__device__ __align__(16) __half g_woh [(size_t)CURD*FEAT_];
__device__ __align__(16) __half g_kv2[(size_t)B_*2*FEAT_];
__device__ __align__(16) __half g_kv3[(size_t)B_*2*FEAT_];
__device__ __align__(16) __half g_att[(size_t)B_*FEAT_];
__device__ __align__(16) float  g_y  [(size_t)B_*CURD];

// ---------------- helpers ----------------
__device__ __forceinline__ void cpa16(uint32_t s, const void* g) {
    asm volatile("cp.async.cg.shared.global [%0], [%1], 16;\n" :: "r"(s), "l"(g));
}

__device__ __forceinline__ void ldsm4(uint32_t* r, uint32_t addr) {
    asm volatile("ldmatrix.sync.aligned.m8n8.x4.shared.b16 {%0,%1,%2,%3}, [%4];"
        : "=r"(r[0]), "=r"(r[1]), "=r"(r[2]), "=r"(r[3]) : "r"(addr));
}

__device__ __forceinline__ void mma_f16(float* c, const uint32_t* a, const uint32_t* b) {
    asm volatile(
        "mma.sync.aligned.m16n8k16.row.col.f32.f16.f16.f32 "
        "{%0,%1,%2,%3}, {%4,%5,%6,%7}, {%8,%9}, {%0,%1,%2,%3};"
        : "+f"(c[0]), "+f"(c[1]), "+f"(c[2]), "+f"(c[3])
        : "r"(a[0]), "r"(a[1]), "r"(a[2]), "r"(a[3]),
          "r"(b[0]), "r"(b[1]));
}

__device__ __forceinline__ uint32_t mixh2(uint32_t va, uint32_t vb, float w2, float w3) {
    float2 a = __half22float2(*(__half2*)&va);
    float2 b = __half22float2(*(__half2*)&vb);
    __half2 o = __floats2half2_rn(w2*a.x + w3*b.x, w2*a.y + w3*b.y);
    return *(uint32_t*)&o;
}

// ---------------- fp32 -> fp16 conversions (merged launches) ----------------
__global__ void convA_kernel(const float* __restrict__ i0, __half* o0,
                             const float* __restrict__ i1, __half* o1,
                             const float* __restrict__ i2, __half* o2) {
    const long long n4 = (long long)B_*2048/4;
    const float* in; __half* out;
    if      (blockIdx.z == 0) { in = i0; out = o0; }
    else if (blockIdx.z == 1) { in = i1; out = o1; }
    else                      { in = i2; out = o2; }
    long long i  = blockIdx.x * (long long)blockDim.x + threadIdx.x;
    long long st = (long long)gridDim.x * blockDim.x;
    const float4* in4 = (const float4*)in;
    __half2* oo = (__half2*)out;
    for (; i < n4; i += st) {
        float4 v = in4[i];
        oo[2*i]   = __floats2half2_rn(v.x, v.y);
        oo[2*i+1] = __floats2half2_rn(v.z, v.w);
    }
}

__global__ void convW_kernel(const float* __restrict__ i0, __half* o0,
                             const float* __restrict__ i1, __half* o1,
                             const float* __restrict__ i2, __half* o2,
                             const float* __restrict__ i3, __half* o3,
                             const float* __restrict__ i4, __half* o4,
                             const float* __restrict__ i5, __half* o5) {
    const long long n4 = (long long)2048*2048/4;
    const float* in; __half* out;
    switch (blockIdx.z) {
        case 0: in = i0; out = o0; break;
        case 1: in = i1; out = o1; break;
        case 2: in = i2; out = o2; break;
        case 3: in = i3; out = o3; break;
        case 4: in = i4; out = o4; break;
        default: in = i5; out = o5; break;
    }
    long long i  = blockIdx.x * (long long)blockDim.x + threadIdx.x;
    long long st = (long long)gridDim.x * blockDim.x;
    const float4* in4 = (const float4*)in;
    __half2* oo = (__half2*)out;
    for (; i < n4; i += st) {
        float4 v = in4[i];
        oo[2*i]   = __floats2half2_rn(v.x, v.y);
        oo[2*i+1] = __floats2half2_rn(v.z, v.w);
    }
}

// ============ shared mainloop fragment (macro-free, inlined) ===============
// Computes acc[4][4][4] for CTA tile (mb,nb): rows mb*128.., cols nloc0.. of W.
// R8-validated: 2-stage cp.async, SW128 swizzle, ldmatrix, warp tile 64x32.
struct FragCtx {
    uint32_t sbase;
    int srow, scol; uint32_t sxor;
    uint32_t aRow, aKoff, bRow, bKoff, fxor;
    int wm, wn, qr, qc, warp, lane;
};

__device__ __forceinline__ void frag_init(FragCtx& f, uint32_t sbase) {
    const int tid = threadIdx.x;
    f.sbase = sbase;
    f.warp = tid >> 5; f.lane = tid & 31;
    f.wm = f.warp & 1; f.wn = f.warp >> 1;
    f.qr = f.lane >> 2; f.qc = f.lane & 3;
    f.srow = tid >> 1; f.scol = (tid & 1) * 64;
    f.sxor = (uint32_t)((f.srow & 7) << 4);
    const int j = f.lane >> 3, rr = f.lane & 7;
    f.fxor = (uint32_t)(rr << 4);
    f.aRow  = (uint32_t)(f.wm*64 + (j&1)*8 + rr);
    f.aKoff = (uint32_t)((j>>1)*16);
    f.bRow  = (uint32_t)(f.wn*32 + (j>>1)*8 + rr);
    f.bKoff = (uint32_t)((j&1)*16);
}

__device__ __forceinline__ void gemm_mainloop(
    const FragCtx& f, const __half* Ag, const __half* Bg, int K,
    float acc[4][4][4])
{
    #pragma unroll
    for (int i = 0; i < 4; i++)
        #pragma unroll
        for (int jn = 0; jn < 4; jn++)
            #pragma unroll
            for (int l = 0; l < 4; l++) acc[i][jn][l] = 0.f;

    const int KT = K / BK;
    // prologue: stage 0
    {
        const uint32_t sA = f.sbase, sB = f.sbase + A_STAGE;
        #pragma unroll
        for (int i = 0; i < 4; i++) {
            uint32_t c = ((uint32_t)(f.scol + i*16)) ^ f.sxor;
            cpa16(sA + f.srow*128 + c, Ag + i*8);
            cpa16(sB + f.srow*128 + c, Bg + i*8);
        }
        asm volatile("cp.async.commit_group;\n" ::);
        asm volatile("cp.async.wait_group 0;\n" ::);
        __syncthreads();
    }
    int buf = 0;
    for (int kt = 0; kt < KT; kt++) {
        if (kt + 1 < KT) {
            const int nbuf = buf ^ 1;
            const uint32_t sA = f.sbase + nbuf*STAGE_B, sB = sA + A_STAGE;
            const __half* Agk = Ag + (kt+1)*BK;
            const __half* Bgk = Bg + (kt+1)*BK;
            #pragma unroll
            for (int i = 0; i < 4; i++) {
                uint32_t c = ((uint32_t)(f.scol + i*16)) ^ f.sxor;
                cpa16(sA + f.srow*128 + c, Agk + i*8);
                cpa16(sB + f.srow*128 + c, Bgk + i*8);
            }
            asm volatile("cp.async.commit_group;\n" ::);
        }
        const uint32_t aBase = f.sbase + buf*STAGE_B + f.aRow*128;
        const uint32_t bBase = f.sbase + buf*STAGE_B + A_STAGE + f.bRow*128;
        #pragma unroll
        for (int ks = 0; ks < BK/16; ks++) {
            uint32_t afr[4][4];
            const uint32_t ac = ((uint32_t)(ks*32) + f.aKoff) ^ f.fxor;
            #pragma unroll
            for (int mt = 0; mt < 4; mt++)
                ldsm4(afr[mt], aBase + mt*16*128 + ac);
            uint32_t bfr[8];
            const uint32_t bc = ((uint32_t)(ks*32) + f.bKoff) ^ f.fxor;
            ldsm4(bfr,     bBase + bc);
            ldsm4(bfr + 4, bBase + 16*128 + bc);
            #pragma unroll
            for (int mt = 0; mt < 4; mt++)
                #pragma unroll
                for (int nt = 0; nt < 4; nt++)
                    mma_f16(acc[mt][nt], afr[mt], bfr + nt*2);
        }
        asm volatile("cp.async.wait_group 0;\n" ::);
        __syncthreads();
        buf ^= 1;
    }
}

// ---------------- kv projection GEMM (fp16 out, W split) -------------------
__global__ __launch_bounds__(NTHREADS, 2)
void gemm_kv_kernel(const __half* __restrict__ A,
                    const __half* __restrict__ W0, const __half* __restrict__ W1,
                    const float* __restrict__ bias0, const float* __restrict__ bias1,
                    __half* __restrict__ C) {
    extern __shared__ __align__(1024) char smem[];
    FragCtx f; frag_init(f, (uint32_t)__cvta_generic_to_shared(smem));
    const int nb = blockIdx.x, mb = blockIdx.y;
    const int N = 2*FEAT_, K = FEAT_;
    const __half* Wp; const float* biasP; int nloc0;
    if (nb*BN < FEAT_) { Wp = W0; biasP = bias0; nloc0 = nb*BN; }
    else               { Wp = W1; biasP = bias1; nloc0 = nb*BN - FEAT_; }
    const __half* Ag = A  + (size_t)(mb*BM + f.srow)*K + f.scol/2;
    const __half* Bg = Wp + (size_t)(nloc0 + f.srow)*K + f.scol/2;

    float acc[4][4][4];
    gemm_mainloop(f, Ag, Bg, K, acc);

    float bv0[4], bv1[4];
    #pragma unroll
    for (int nt = 0; nt < 4; nt++) {
        int cl = nloc0 + f.wn*32 + nt*8 + f.qc*2;
        bv0[nt] = biasP[cl]; bv1[nt] = biasP[cl + 1];
    }
    #pragma unroll
    for (int mt = 0; mt < 4; mt++) {
        int r0 = mb*BM + f.wm*64 + mt*16 + f.qr;
        #pragma unroll
        for (int nt = 0; nt < 4; nt++) {
            int c0 = nb*BN + f.wn*32 + nt*8 + f.qc*2;
            size_t o0 = (size_t)r0*N + c0;
            size_t o1 = o0 + (size_t)8*N;
            *(__half2*)(C + o0) = __floats2half2_rn(acc[mt][nt][0]+bv0[nt], acc[mt][nt][1]+bv1[nt]);
            *(__half2*)(C + o1) = __floats2half2_rn(acc[mt][nt][2]+bv0[nt], acc[mt][nt][3]+bv1[nt]);
        }
    }
}

// ---------------- q GEMM + fused attention epilogue -------------------------
// nb == head index (BN == HDIM). Epilogue: q tile -> smem fp32, per-row dots
// vs k2/k3, softmax -> wout + smem, attn tile = w2*v2 + w3*v3 -> attn (fp16).
__global__ __launch_bounds__(NTHREADS, 2)
void gemm_qattn_kernel(const __half* __restrict__ xh,
                       const __half* __restrict__ wq,
                       const float* __restrict__ bq,
                       const __half* __restrict__ kv2,
                       const __half* __restrict__ kv3,
                       __half* __restrict__ attn,
                       float* __restrict__ wout) {
    extern __shared__ __align__(1024) char smem[];
    __shared__ float ws2[128], ws3[128];
    FragCtx f; frag_init(f, (uint32_t)__cvta_generic_to_shared(smem));
    const int nb = blockIdx.x, mb = blockIdx.y;   // nb = head
    const int K = CURD;
    const int nloc0 = nb*BN;
    const __half* Ag = xh + (size_t)(mb*BM + f.srow)*K + f.scol/2;
    const __half* Bg = wq + (size_t)(nloc0 + f.srow)*K + f.scol/2;

    float acc[4][4][4];
    gemm_mainloop(f, Ag, Bg, K, acc);
    // mainloop ends with __syncthreads(): smem safe to reuse.

    // ---- phase 1: q tile (fp32, +bias) into smem ----
    float* qs = (float*)smem;
    float bv0[4], bv1[4];
    #pragma unroll
    for (int nt = 0; nt < 4; nt++) {
        int cl = nloc0 + f.wn*32 + nt*8 + f.qc*2;
        bv0[nt] = bq[cl]; bv1[nt] = bq[cl + 1];
    }
    #pragma unroll
    for (int mt = 0; mt < 4; mt++) {
        int rl = f.wm*64 + mt*16 + f.qr;
        #pragma unroll
        for (int nt = 0; nt < 4; nt++) {
            int c0 = f.wn*32 + nt*8 + f.qc*2;
            qs[rl*QS_STRIDE + c0]       = acc[mt][nt][0] + bv0[nt];
            qs[rl*QS_STRIDE + c0 + 1]   = acc[mt][nt][1] + bv1[nt];
            qs[(rl+8)*QS_STRIDE + c0]   = acc[mt][nt][2] + bv0[nt];
            qs[(rl+8)*QS_STRIDE + c0+1] = acc[mt][nt][3] + bv1[nt];
        }
    }
    __syncthreads();

    // ---- phase 2: per-row dots vs k2/k3, softmax ----
    const float scale = 0.08838834764831845f;   // 1/sqrt(128)
    const size_t rowbase = (size_t)mb * BM;
    const int koff = nb*HDIM + f.lane*4;
    for (int rg = 0; rg < 16; rg += 4) {
        const int r0 = f.warp*16 + rg;
        uint2 K2[4], K3[4]; float4 Q4[4];
        #pragma unroll
        for (int i = 0; i < 4; i++) {
            size_t grow = rowbase + r0 + i;
            K2[i] = *(const uint2*)(kv2 + grow*(2*FEAT_) + koff);
            K3[i] = *(const uint2*)(kv3 + grow*(2*FEAT_) + koff);
            Q4[i] = *(const float4*)(qs + (r0+i)*QS_STRIDE + f.lane*4);
        }
        float s2[4], s3[4];
        #pragma unroll
        for (int i = 0; i < 4; i++) {
            float2 a0 = __half22float2(*(__half2*)&K2[i].x);
            float2 a1 = __half22float2(*(__half2*)&K2[i].y);
            s2[i] = Q4[i].x*a0.x + Q4[i].y*a0.y + Q4[i].z*a1.x + Q4[i].w*a1.y;
            float2 c0 = __half22float2(*(__half2*)&K3[i].x);
            float2 c1 = __half22float2(*(__half2*)&K3[i].y);
            s3[i] = Q4[i].x*c0.x + Q4[i].y*c0.y + Q4[i].z*c1.x + Q4[i].w*c1.y;
        }
        #pragma unroll
        for (int i = 0; i < 4; i++) {
            #pragma unroll
            for (int o = 16; o; o >>= 1) {
                s2[i] += __shfl_xor_sync(0xffffffffu, s2[i], o);
                s3[i] += __shfl_xor_sync(0xffffffffu, s3[i], o);
            }
        }
        if (f.lane == 0) {
            #pragma unroll
            for (int i = 0; i < 4; i++) {
                float a = s2[i]*scale, b = s3[i]*scale;
                float m  = fmaxf(a, b);
                float e2 = expf(a - m), e3 = expf(b - m);
                float inv = 1.f / (e2 + e3);
                float w2 = e2*inv, w3 = e3*inv;
                ws2[r0+i] = w2; ws3[r0+i] = w3;
                size_t grow = rowbase + r0 + i;
                *(float2*)(wout + (grow*HEADS_ + nb)*2) = make_float2(w2, w3);
            }
        }
    }
    __syncthreads();

    // ---- phase 3: attn tile = w2*v2 + w3*v3 (fp16) ----
    for (int it = threadIdx.x; it < 128*16; it += NTHREADS) {
        const int rl = it >> 4, seg = it & 15;
        const size_t grow = rowbase + rl;
        const int col = nb*HDIM + seg*8;
        const float w2 = ws2[rl], w3 = ws3[rl];
        uint4 V2 = *(const uint4*)(kv2 + grow*(2*FEAT_) + FEAT_ + col);
        uint4 V3 = *(const uint4*)(kv3 + grow*(2*FEAT_) + FEAT_ + col);
        uint4 O;
        O.x = mixh2(V2.x, V3.x, w2, w3);
        O.y = mixh2(V2.y, V3.y, w2, w3);
        O.z = mixh2(V2.z, V3.z, w2, w3);
        O.w = mixh2(V2.w, V3.w, w2, w3);
        *(uint4*)(attn + grow*FEAT_ + col) = O;
    }
}

// ---------------- Wo GEMM: y = x + attn @ Wo^T + bo (fp32 out) -------------
__global__ __launch_bounds__(NTHREADS, 2)
void gemm_wo_kernel(const __half* __restrict__ A,
                    const __half* __restrict__ W,
                    const float* __restrict__ bias,
                    const float* __restrict__ res,
                    float* __restrict__ C) {
    extern __shared__ __align__(1024) char smem[];
    FragCtx f; frag_init(f, (uint32_t)__cvta_generic_to_shared(smem));
    const int nb = blockIdx.x, mb = blockIdx.y;
    const int N = CURD, K = FEAT_;
    const int nloc0 = nb*BN;
    const __half* Ag = A + (size_t)(mb*BM + f.srow)*K + f.scol/2;
    const __half* Bg = W + (size_t)(nloc0 + f.srow)*K + f.scol/2;

    float acc[4][4][4];
    gemm_mainloop(f, Ag, Bg, K, acc);

    float bv0[4], bv1[4];
    #pragma unroll
    for (int nt = 0; nt < 4; nt++) {
        int cl = nloc0 + f.wn*32 + nt*8 + f.qc*2;
        bv0[nt] = bias[cl]; bv1[nt] = bias[cl + 1];
    }
    #pragma unroll
    for (int mt = 0; mt < 4; mt++) {
        int r0 = mb*BM + f.wm*64 + mt*16 + f.qr;
        #pragma unroll
        for (int nt = 0; nt < 4; nt++) {
            int c0 = nloc0 + f.wn*32 + nt*8 + f.qc*2;
            size_t o0 = (size_t)r0*N + c0;
            size_t o1 = o0 + (size_t)8*N;
            float v0 = acc[mt][nt][0] + bv0[nt] + res[o0];
            float v1 = acc[mt][nt][1] + bv1[nt] + res[o0+1];
            float v2 = acc[mt][nt][2] + bv0[nt] + res[o1];
            float v3 = acc[mt][nt][3] + bv1[nt] + res[o1+1];
            *(float2*)(C + o0) = make_float2(v0, v1);
            *(float2*)(C + o1) = make_float2(v2, v3);
        }
    }
}

// ---------------- LayerNorm: one block per row ----------------------------
__global__ void ln_kernel(const float* __restrict__ y,
                          const float* __restrict__ lw,
                          const float* __restrict__ lb,
                          float* __restrict__ out) {
    __shared__ float shs[8], shq[8];
    int row = blockIdx.x, t = threadIdx.x;
    const float4* yr = (const float4*)(y + (size_t)row*CURD);
    float4 a = yr[t];
    float4 b = yr[256 + t];
    float s  = a.x+a.y+a.z+a.w + b.x+b.y+b.z+b.w;
    float qq = a.x*a.x+a.y*a.y+a.z*a.z+a.w*a.w
             + b.x*b.x+b.y*b.y+b.z*b.z+b.w*b.w;
    #pragma unroll
    for (int o = 16; o; o >>= 1) {
        s  += __shfl_xor_sync(0xffffffffu, s,  o);
        qq += __shfl_xor_sync(0xffffffffu, qq, o);
    }
    int warp = t >> 5;
    if ((t & 31) == 0) { shs[warp] = s; shq[warp] = qq; }
    __syncthreads();
    float S = 0.f, Q = 0.f;
    #pragma unroll
    for (int i = 0; i < 8; i++) { S += shs[i]; Q += shq[i]; }
    float mean = S * (1.f/2048.f);
    float inv  = rsqrtf(Q * (1.f/2048.f) - mean*mean + 1e-5f);

    const float4* lw4 = (const float4*)lw;
    const float4* lb4 = (const float4*)lb;
    float4* orow = (float4*)(out + (size_t)row*CURD);
    float4 w, z, o4;
    w = lw4[t];       z = lb4[t];
    o4.x = w.x*(a.x-mean)*inv + z.x;
    o4.y = w.y*(a.y-mean)*inv + z.y;
    o4.z = w.z*(a.z-mean)*inv + z.z;
    o4.w = w.w*(a.w-mean)*inv + z.w;
    orow[t] = o4;
    w = lw4[256+t];   z = lb4[256+t];
    o4.x = w.x*(b.x-mean)*inv + z.x;
    o4.y = w.y*(b.y-mean)*inv + z.y;
    o4.z = w.z*(b.z-mean)*inv + z.z;
    o4.w = w.w*(b.w-mean)*inv + z.w;
    orow[256+t] = o4;
}

// ---------------- launch ---------------------------------------------------
extern "C" void kernel_launch(void* const* d_in, const int* in_sizes, int n_in,
                              void* d_out, int out_size) {
    const float* x   = (const float*)d_in[0];
    const float* v2  = (const float*)d_in[1];
    const float* v3  = (const float*)d_in[2];
    const float* Wq  = (const float*)d_in[3];
    const float* bq  = (const float*)d_in[4];
    const float* Wk2 = (const float*)d_in[5];
    const float* bk2 = (const float*)d_in[6];
    const float* Wk3 = (const float*)d_in[7];
    const float* bk3 = (const float*)d_in[8];
    const float* Wv2 = (const float*)d_in[9];
    const float* bv2 = (const float*)d_in[10];
    const float* Wv3 = (const float*)d_in[11];
    const float* bv3 = (const float*)d_in[12];
    const float* Wo  = (const float*)d_in[13];
    const float* bo  = (const float*)d_in[14];
    const float* lw  = (const float*)d_in[15];
    const float* lb  = (const float*)d_in[16];
    float* out = (float*)d_out;

    __half *xh, *v2h, *v3h, *wqh, *wk2h, *wv2h, *wk3h, *wv3h, *woh;
    __half *kv2, *kv3, *attn;
    float *yb;
    cudaGetSymbolAddress((void**)&xh,   g_xh);
    cudaGetSymbolAddress((void**)&v2h,  g_v2h);
    cudaGetSymbolAddress((void**)&v3h,  g_v3h);
    cudaGetSymbolAddress((void**)&wqh,  g_wqh);
    cudaGetSymbolAddress((void**)&wk2h, g_wk2h);
    cudaGetSymbolAddress((void**)&wv2h, g_wv2h);
    cudaGetSymbolAddress((void**)&wk3h, g_wk3h);
    cudaGetSymbolAddress((void**)&wv3h, g_wv3h);
    cudaGetSymbolAddress((void**)&woh,  g_woh);
    cudaGetSymbolAddress((void**)&kv2,  g_kv2);
    cudaGetSymbolAddress((void**)&kv3,  g_kv3);
    cudaGetSymbolAddress((void**)&attn, g_att);
    cudaGetSymbolAddress((void**)&yb,   g_y);

    cudaFuncSetAttribute((const void*)gemm_kv_kernel,
                         cudaFuncAttributeMaxDynamicSharedMemorySize, SMEM_BYTES);
    cudaFuncSetAttribute((const void*)gemm_qattn_kernel,
                         cudaFuncAttributeMaxDynamicSharedMemorySize, SMEM_QATTN);
    cudaFuncSetAttribute((const void*)gemm_wo_kernel,
                         cudaFuncAttributeMaxDynamicSharedMemorySize, SMEM_BYTES);

    // conversions (2 merged launches)
    convA_kernel<<<dim3(2048, 1, 3), 256>>>(x, xh, v2, v2h, v3, v3h);
    convW_kernel<<<dim3(1024, 1, 6), 256>>>(Wq, wqh, Wk2, wk2h, Wv2, wv2h,
                                            Wk3, wk3h, Wv3, wv3h, Wo, woh);

    dim3 blk(NTHREADS);
    // [k2 | v2] and [k3 | v3] projections (must precede q+attn)
    gemm_kv_kernel<<<dim3(2*FEAT_/BN, B_/BM), blk, SMEM_BYTES>>>(
        v2h, wk2h, wv2h, bk2, bv2, kv2);
    gemm_kv_kernel<<<dim3(2*FEAT_/BN, B_/BM), blk, SMEM_BYTES>>>(
        v3h, wk3h, wv3h, bk3, bv3, kv3);

    // q projection with fused attention epilogue -> attn + wout
    size_t woff = (size_t)out_size - (size_t)B_*HEADS_*2;
    gemm_qattn_kernel<<<dim3(FEAT_/BN, B_/BM), blk, SMEM_QATTN>>>(
        xh, wqh, bq, kv2, kv3, attn, out + woff);

    // y = x + attn @ Wo^T + bo
    gemm_wo_kernel<<<dim3(CURD/BN, B_/BM), blk, SMEM_BYTES>>>(
        attn, woh, bo, x, yb);

    // LayerNorm -> d_out
    ln_kernel<<<B_, 256>>>(yb, lw, lb, out);
}